// round 1
// baseline (speedup 1.0000x reference)
#include <cuda_runtime.h>

#define N_NODES 8192
#define K_MAT   4
#define E_EDGES 262144
#define D       128

// ---- scratch (device globals; no allocation allowed) ----
__device__ float g_w[K_MAT];           // softmax weights
__device__ int   g_is64;               // 1 if edge_index dumped as int64
__device__ float g_ew[E_EDGES];        // mixed edge weights
__device__ float g_dinv[N_NODES];      // deg, then rsqrt(deg) in place
__device__ float g_xw[N_NODES * D];    // x @ W^T

// softmax over 4 logits + flag init (1 thread)
__global__ void k_init(const float* __restrict__ wl) {
    float m = wl[0];
    #pragma unroll
    for (int k = 1; k < K_MAT; k++) m = fmaxf(m, wl[k]);
    float e[K_MAT], s = 0.f;
    #pragma unroll
    for (int k = 0; k < K_MAT; k++) { e[k] = expf(wl[k] - m); s += e[k]; }
    #pragma unroll
    for (int k = 0; k < K_MAT; k++) g_w[k] = e[k] / s;
    g_is64 = 1;
}

// int32-vs-int64 detection: if int64 (values < 8192, non-negative) every odd
// 32-bit word of the first E 64-bit entries is 0; if int32 those words are
// live index values (random in [0,8192), overwhelmingly nonzero somewhere).
__global__ void k_detect(const int* __restrict__ ei) {
    int i = blockIdx.x * blockDim.x + threadIdx.x;
    if (i < E_EDGES) {
        if (ei[2 * i + 1] != 0) g_is64 = 0;   // benign race: all writers write 0
    }
}

__global__ void k_deginit() {
    int i = blockIdx.x * blockDim.x + threadIdx.x;
    if (i < N_NODES) g_dinv[i] = 1.0f;        // self-loop contributes weight 1
}

// per-edge: gather 4 entries of A_list, mix, accumulate degree at col
__global__ void k_edges(const float* __restrict__ A, const int* __restrict__ ei) {
    int e = blockIdx.x * blockDim.x + threadIdx.x;
    if (e >= E_EDGES) return;
    int r, c;
    if (g_is64) { r = ei[2 * e]; c = ei[2 * (E_EDGES + e)]; }
    else        { r = ei[e];     c = ei[E_EDGES + e]; }
    const size_t NN = (size_t)N_NODES * N_NODES;
    size_t base = (size_t)r * N_NODES + (size_t)c;
    float a0 = __ldg(A + base);
    float a1 = __ldg(A + base + NN);
    float a2 = __ldg(A + base + 2 * NN);
    float a3 = __ldg(A + base + 3 * NN);
    float ew = g_w[0] * a0 + g_w[1] * a1 + g_w[2] * a2 + g_w[3] * a3;
    g_ew[e] = ew;
    atomicAdd(&g_dinv[c], ew);
}

__global__ void k_dinv() {
    int i = blockIdx.x * blockDim.x + threadIdx.x;
    if (i < N_NODES) {
        float d = g_dinv[i];
        g_dinv[i] = (d > 0.f) ? rsqrtf(fmaxf(d, 1e-30f)) : 0.f;
    }
}

// xw = x @ W^T   (W is [D_OUT, D_IN] row-major). 16 rows per block, 128 thr.
__global__ void k_gemm(const float* __restrict__ x, const float* __restrict__ Wm) {
    __shared__ float xs[16 * D];     // 8 KB
    __shared__ float ws[D * 33];     // padded to kill bank conflicts (~17 KB)
    const int tid  = threadIdx.x;    // 0..127 ; o = output column
    const int row0 = blockIdx.x * 16;

    for (int i = tid; i < 16 * D; i += 128)
        xs[i] = x[(size_t)row0 * D + i];

    float acc[16];
    #pragma unroll
    for (int r = 0; r < 16; r++) acc[r] = 0.f;

    const int o = tid;
    for (int d0 = 0; d0 < D; d0 += 32) {
        __syncthreads();             // guards xs (first iter) + ws reuse
        for (int j = tid; j < D * 32; j += 128) {
            int row = j >> 5, cc = j & 31;    // warp reads 128B contiguous
            ws[row * 33 + cc] = Wm[row * D + d0 + cc];
        }
        __syncthreads();
        #pragma unroll
        for (int dd = 0; dd < 32; dd++) {
            float wv = ws[o * 33 + dd];
            #pragma unroll
            for (int r = 0; r < 16; r++)
                acc[r] += xs[r * D + d0 + dd] * wv;   // xs read = broadcast
        }
    }
    #pragma unroll
    for (int r = 0; r < 16; r++)
        g_xw[(size_t)(row0 + r) * D + o] = acc[r];
}

// out[i] = b + dinv[i]^2 * xw[i]   (self-loop message + bias)
__global__ void k_outinit(const float* __restrict__ b, float* __restrict__ out) {
    int i = blockIdx.x * blockDim.x + threadIdx.x;   // N*D total
    int node = i >> 7, o = i & 127;
    float di = g_dinv[node];
    out[i] = b[o] + di * di * g_xw[i];
}

// one warp per edge; 32 lanes x float4 = 128 dims; vector L2 reduction
__global__ void k_scatter(const int* __restrict__ ei, float* __restrict__ out) {
    int gtid = blockIdx.x * blockDim.x + threadIdx.x;
    int e    = gtid >> 5;
    int lane = threadIdx.x & 31;
    if (e >= E_EDGES) return;
    int r, c;
    if (g_is64) { r = ei[2 * e]; c = ei[2 * (E_EDGES + e)]; }
    else        { r = ei[e];     c = ei[E_EDGES + e]; }
    float norm = g_dinv[r] * g_ew[e] * g_dinv[c];
    float4 v = ((const float4*)(g_xw + (size_t)r * D))[lane];
    float4* dst = (float4*)(out + (size_t)c * D) + lane;
    asm volatile("red.global.add.v4.f32 [%0], {%1,%2,%3,%4};"
                 :: "l"(dst),
                    "f"(norm * v.x), "f"(norm * v.y),
                    "f"(norm * v.z), "f"(norm * v.w)
                 : "memory");
}

extern "C" void kernel_launch(void* const* d_in, const int* in_sizes, int n_in,
                              void* d_out, int out_size) {
    const float* x  = (const float*)d_in[0];
    const float* A  = (const float*)d_in[1];
    const int*   ei = (const int*)  d_in[2];
    const float* wl = (const float*)d_in[3];
    const float* Wm = (const float*)d_in[4];
    const float* b  = (const float*)d_in[5];
    float* out = (float*)d_out;

    k_init   <<<1, 1>>>(wl);
    k_detect <<<E_EDGES / 256, 256>>>(ei);
    k_deginit<<<N_NODES / 256, 256>>>();
    k_edges  <<<E_EDGES / 256, 256>>>(A, ei);
    k_dinv   <<<N_NODES / 256, 256>>>();
    k_gemm   <<<N_NODES / 16, 128>>>(x, Wm);
    k_outinit<<<(N_NODES * D) / 256, 256>>>(b, out);
    k_scatter<<<(E_EDGES * 32) / 256, 256>>>(ei, out);
}

// round 2
// speedup vs baseline: 1.1894x; 1.1894x over previous
#include <cuda_runtime.h>

#define N_NODES 8192
#define K_MAT   4
#define E_EDGES 262144
#define D       128
#define GEMM_BLOCKS 512
#define EDGE_BLOCKS (E_EDGES / 128)

// ---- scratch (device globals) ----
__device__ float g_w[K_MAT];
__device__ int   g_is64;
__device__ float g_ew[E_EDGES];
__device__ int   g_rc[E_EDGES];          // (r<<13)|c
__device__ float g_deg[N_NODES];
__device__ float g_dinv[N_NODES];
__device__ int   g_cnt[N_NODES];         // histogram, then reused as cursor
__device__ int   g_off[N_NODES + 1];     // bucket offsets
__device__ uint2 g_rm[E_EDGES];          // sorted (r, norm) pairs
__device__ float g_xw[N_NODES * D];

__global__ void k_init(const float* __restrict__ wl) {
    float m = wl[0];
    #pragma unroll
    for (int k = 1; k < K_MAT; k++) m = fmaxf(m, wl[k]);
    float e[K_MAT], s = 0.f;
    #pragma unroll
    for (int k = 0; k < K_MAT; k++) { e[k] = expf(wl[k] - m); s += e[k]; }
    #pragma unroll
    for (int k = 0; k < K_MAT; k++) g_w[k] = e[k] / s;
    g_is64 = 1;
}

// detect int32-vs-int64 dump + init deg/cnt
__global__ void k_prep(const int* __restrict__ ei) {
    int i = blockIdx.x * blockDim.x + threadIdx.x;
    if (i < E_EDGES) {
        if (ei[2 * i + 1] != 0) g_is64 = 0;   // benign race: all write 0
    }
    if (i < N_NODES) { g_deg[i] = 1.0f; g_cnt[i] = 0; }
}

// fused: blocks [0,512) = gemm (xw = x @ W^T), blocks [512,...) = edge gather
__global__ void __launch_bounds__(128) k_fused(const float* __restrict__ x,
                                               const float* __restrict__ Wm,
                                               const float* __restrict__ A,
                                               const int*   __restrict__ ei) {
    __shared__ float xs[16 * D];     // 8 KB
    __shared__ float ws[32 * 33];    // 4.2 KB (32 W-rows per chunk, padded)
    const int tid = threadIdx.x;

    if (blockIdx.x < GEMM_BLOCKS) {
        const int row0 = blockIdx.x * 16;
        for (int i = tid; i < 16 * D; i += 128)
            xs[i] = x[(size_t)row0 * D + i];
        float acc[16];
        #pragma unroll
        for (int r = 0; r < 16; r++) acc[r] = 0.f;
        const int o = tid;
        for (int d0 = 0; d0 < D; d0 += 32) {
            __syncthreads();
            // chunk: rows of W restricted to cols [d0,d0+32) — but we need
            // per-output-row W[o][d0..]; stage all 128 rows' 32-col slice
            for (int j = tid; j < 128 * 32; j += 128) {
                int row = j >> 5, cc = j & 31;
                if (j < 32 * 33) {} // no-op, keep compiler quiet
                // stage into ws only 32 rows at a time is insufficient; use
                // direct layout: ws2 covers rows [0,128) cols 32 => too big.
                // Instead reuse xs trick: stage into a 128x32 region across
                // both smem arrays is messy — use simple scheme below.
                (void)row; (void)cc;
                break;
            }
            break;
        }
        // --- simpler, proven scheme from R1 (full W slice staging) ---
        {
            __shared__ float ws_full[D * 33];  // 16.9 KB
            float accv[16];
            #pragma unroll
            for (int r = 0; r < 16; r++) accv[r] = 0.f;
            const int oo = tid;
            for (int d0 = 0; d0 < D; d0 += 32) {
                __syncthreads();
                for (int j = tid; j < D * 32; j += 128) {
                    int row = j >> 5, cc = j & 31;
                    ws_full[row * 33 + cc] = Wm[row * D + d0 + cc];
                }
                __syncthreads();
                #pragma unroll
                for (int dd = 0; dd < 32; dd++) {
                    float wv = ws_full[oo * 33 + dd];
                    #pragma unroll
                    for (int r = 0; r < 16; r++)
                        accv[r] += xs[r * D + d0 + dd] * wv;
                }
            }
            #pragma unroll
            for (int r = 0; r < 16; r++)
                g_xw[(size_t)(row0 + r) * D + oo] = accv[r];
        }
    } else {
        int e = (blockIdx.x - GEMM_BLOCKS) * 128 + tid;
        if (e >= E_EDGES) return;
        int r, c;
        if (g_is64) { r = ei[2 * e]; c = ei[2 * (E_EDGES + e)]; }
        else        { r = ei[e];     c = ei[E_EDGES + e]; }
        const size_t NN = (size_t)N_NODES * N_NODES;
        size_t base = (size_t)r * N_NODES + (size_t)c;
        float a0 = __ldg(A + base);
        float a1 = __ldg(A + base + NN);
        float a2 = __ldg(A + base + 2 * NN);
        float a3 = __ldg(A + base + 3 * NN);
        float ew = g_w[0] * a0 + g_w[1] * a1 + g_w[2] * a2 + g_w[3] * a3;
        g_ew[e] = ew;
        g_rc[e] = (r << 13) | c;
        atomicAdd(&g_deg[c], ew);
        atomicAdd(&g_cnt[c], 1);
    }
}

// one block: exclusive scan of 8192 counts -> offsets; dinv; zero cursors
__global__ void k_scan() {
    __shared__ int sm[1024];
    int tid = threadIdx.x;
    int base = tid * 8;
    int loc[8], s = 0;
    #pragma unroll
    for (int j = 0; j < 8; j++) { loc[j] = g_cnt[base + j]; s += loc[j]; }
    sm[tid] = s;
    __syncthreads();
    for (int off = 1; off < 1024; off <<= 1) {
        int v = sm[tid];
        int add = (tid >= off) ? sm[tid - off] : 0;
        __syncthreads();
        sm[tid] = v + add;
        __syncthreads();
    }
    int run = sm[tid] - s;          // exclusive
    #pragma unroll
    for (int j = 0; j < 8; j++) { g_off[base + j] = run; run += loc[j]; }
    if (tid == 1023) g_off[N_NODES] = run;
    #pragma unroll
    for (int j = 0; j < 8; j++) {
        float d = g_deg[base + j];
        g_dinv[base + j] = rsqrtf(fmaxf(d, 1e-30f));   // deg >= 1 always
        g_cnt[base + j] = 0;
    }
}

// place edges into destination-sorted buckets with final norm
__global__ void k_place() {
    int e = blockIdx.x * blockDim.x + threadIdx.x;
    if (e >= E_EDGES) return;
    int rc = g_rc[e];
    int r = rc >> 13, c = rc & (N_NODES - 1);
    float m = g_dinv[r] * g_ew[e] * g_dinv[c];
    int pos = g_off[c] + atomicAdd(&g_cnt[c], 1);
    g_rm[pos] = make_uint2((unsigned)r, __float_as_uint(m));
}

// warp per destination node: L2 gather of xw rows, one coalesced store
__global__ void __launch_bounds__(256) k_gather(const float* __restrict__ b,
                                                float* __restrict__ out) {
    int warp = (blockIdx.x * blockDim.x + threadIdx.x) >> 5;
    int lane = threadIdx.x & 31;
    if (warp >= N_NODES) return;
    int c = warp;
    const float4* xw4 = (const float4*)g_xw;
    int j = g_off[c], e = g_off[c + 1];
    float4 acc = make_float4(0.f, 0.f, 0.f, 0.f);
    for (; j + 1 < e; j += 2) {
        uint2 p0 = g_rm[j];
        uint2 p1 = g_rm[j + 1];
        float4 v0 = xw4[(size_t)p0.x * 32 + lane];
        float4 v1 = xw4[(size_t)p1.x * 32 + lane];
        float m0 = __uint_as_float(p0.y);
        float m1 = __uint_as_float(p1.y);
        acc.x += m0 * v0.x + m1 * v1.x;
        acc.y += m0 * v0.y + m1 * v1.y;
        acc.z += m0 * v0.z + m1 * v1.z;
        acc.w += m0 * v0.w + m1 * v1.w;
    }
    if (j < e) {
        uint2 p0 = g_rm[j];
        float4 v0 = xw4[(size_t)p0.x * 32 + lane];
        float m0 = __uint_as_float(p0.y);
        acc.x += m0 * v0.x; acc.y += m0 * v0.y;
        acc.z += m0 * v0.z; acc.w += m0 * v0.w;
    }
    // self-loop + bias
    float di = g_dinv[c];
    float sl = di * di;
    float4 vs = xw4[(size_t)c * 32 + lane];
    float4 bb = ((const float4*)b)[lane];
    acc.x += sl * vs.x + bb.x;
    acc.y += sl * vs.y + bb.y;
    acc.z += sl * vs.z + bb.z;
    acc.w += sl * vs.w + bb.w;
    ((float4*)out)[(size_t)c * 32 + lane] = acc;
}

extern "C" void kernel_launch(void* const* d_in, const int* in_sizes, int n_in,
                              void* d_out, int out_size) {
    const float* x  = (const float*)d_in[0];
    const float* A  = (const float*)d_in[1];
    const int*   ei = (const int*)  d_in[2];
    const float* wl = (const float*)d_in[3];
    const float* Wm = (const float*)d_in[4];
    const float* b  = (const float*)d_in[5];
    float* out = (float*)d_out;

    k_init  <<<1, 1>>>(wl);
    k_prep  <<<E_EDGES / 256, 256>>>(ei);
    k_fused <<<GEMM_BLOCKS + EDGE_BLOCKS, 128>>>(x, Wm, A, ei);
    k_scan  <<<1, 1024>>>();
    k_place <<<E_EDGES / 256, 256>>>();
    k_gather<<<N_NODES / 8, 256>>>(b, out);
}

// round 3
// speedup vs baseline: 1.3491x; 1.1343x over previous
#include <cuda_runtime.h>

#define N_NODES 8192
#define K_MAT   4
#define E_EDGES 262144
#define D       128
#define GEMM_BLOCKS 512
#define EDGE_BLOCKS (E_EDGES / 256)   // 256 edges per block (2 per thread)

// ---- scratch (device globals) ----
__device__ float g_w[K_MAT];
__device__ int   g_is64;
__device__ float g_ew[E_EDGES];
__device__ int   g_rc[E_EDGES];          // (r<<13)|c
__device__ float g_deg[N_NODES];
__device__ float g_dinv[N_NODES];
__device__ int   g_cnt[N_NODES];         // histogram, then cursor
__device__ int   g_off[N_NODES];         // bucket base (arbitrary order)
__device__ int   g_end[N_NODES];         // bucket end
__device__ int   g_total;                // global bucket cursor
__device__ uint2 g_rm[E_EDGES];          // (r, norm) pairs, bucketed by c
__device__ float g_xw[N_NODES * D];

__global__ void k_init(const float* __restrict__ wl) {
    float m = wl[0];
    #pragma unroll
    for (int k = 1; k < K_MAT; k++) m = fmaxf(m, wl[k]);
    float e[K_MAT], s = 0.f;
    #pragma unroll
    for (int k = 0; k < K_MAT; k++) { e[k] = expf(wl[k] - m); s += e[k]; }
    #pragma unroll
    for (int k = 0; k < K_MAT; k++) g_w[k] = e[k] / s;
    g_is64 = 1;
    g_total = 0;
}

// detect int32-vs-int64 dump + init deg/cnt
__global__ void k_prep(const int* __restrict__ ei) {
    int i = blockIdx.x * blockDim.x + threadIdx.x;
    if (i < E_EDGES) {
        if (ei[2 * i + 1] != 0) g_is64 = 0;   // benign race: all write 0
    }
    if (i < N_NODES) { g_deg[i] = 1.0f; g_cnt[i] = 0; }
}

// fused: blocks [0,512) = gemm (xw = x @ W^T), blocks [512,...) = edge mix
__global__ void __launch_bounds__(128) k_fused(const float* __restrict__ x,
                                               const float* __restrict__ Wm,
                                               const float* __restrict__ A,
                                               const int*   __restrict__ ei) {
    const int tid = threadIdx.x;

    if (blockIdx.x < GEMM_BLOCKS) {
        __shared__ float xs[16 * D];       // 8 KB
        __shared__ float ws[D * 33];       // 16.9 KB padded
        const int row0 = blockIdx.x * 16;
        for (int i = tid; i < 16 * D; i += 128)
            xs[i] = x[(size_t)row0 * D + i];
        float acc[16];
        #pragma unroll
        for (int r = 0; r < 16; r++) acc[r] = 0.f;
        const int o = tid;
        for (int d0 = 0; d0 < D; d0 += 32) {
            __syncthreads();
            for (int j = tid; j < D * 32; j += 128) {
                int row = j >> 5, cc = j & 31;
                ws[row * 33 + cc] = Wm[row * D + d0 + cc];
            }
            __syncthreads();
            #pragma unroll
            for (int dd = 0; dd < 32; dd++) {
                float wv = ws[o * 33 + dd];
                #pragma unroll
                for (int r = 0; r < 16; r++)
                    acc[r] += xs[r * D + d0 + dd] * wv;
            }
        }
        #pragma unroll
        for (int r = 0; r < 16; r++)
            g_xw[(size_t)(row0 + r) * D + o] = acc[r];
    } else {
        // 2 edges per thread for higher MLP; sector-granular L2 loads
        const size_t NN = (size_t)N_NODES * N_NODES;
        int ebase = (blockIdx.x - GEMM_BLOCKS) * 256 + tid;
        int is64 = g_is64;
        float w0 = g_w[0], w1 = g_w[1], w2 = g_w[2], w3 = g_w[3];
        int e0 = ebase, e1 = ebase + 128;
        int r0, c0, r1, c1;
        if (is64) {
            r0 = ei[2 * e0]; c0 = ei[2 * (E_EDGES + e0)];
            r1 = ei[2 * e1]; c1 = ei[2 * (E_EDGES + e1)];
        } else {
            r0 = ei[e0]; c0 = ei[E_EDGES + e0];
            r1 = ei[e1]; c1 = ei[E_EDGES + e1];
        }
        size_t b0 = (size_t)r0 * N_NODES + (size_t)c0;
        size_t b1 = (size_t)r1 * N_NODES + (size_t)c1;
        float a00 = __ldcg(A + b0);
        float a01 = __ldcg(A + b0 + NN);
        float a02 = __ldcg(A + b0 + 2 * NN);
        float a03 = __ldcg(A + b0 + 3 * NN);
        float a10 = __ldcg(A + b1);
        float a11 = __ldcg(A + b1 + NN);
        float a12 = __ldcg(A + b1 + 2 * NN);
        float a13 = __ldcg(A + b1 + 3 * NN);
        float ew0 = w0 * a00 + w1 * a01 + w2 * a02 + w3 * a03;
        float ew1 = w0 * a10 + w1 * a11 + w2 * a12 + w3 * a13;
        g_ew[e0] = ew0;  g_rc[e0] = (r0 << 13) | c0;
        g_ew[e1] = ew1;  g_rc[e1] = (r1 << 13) | c1;
        atomicAdd(&g_deg[c0], ew0);
        atomicAdd(&g_cnt[c0], 1);
        atomicAdd(&g_deg[c1], ew1);
        atomicAdd(&g_cnt[c1], 1);
    }
}

// bucket bases via warp-scan + one global atomic per warp (order-free)
__global__ void k_offsets() {
    int i = blockIdx.x * blockDim.x + threadIdx.x;
    if (i >= N_NODES) return;
    int lane = threadIdx.x & 31;
    int cnt = g_cnt[i];
    int v = cnt;                                    // inclusive warp scan
    #pragma unroll
    for (int o = 1; o < 32; o <<= 1) {
        int t = __shfl_up_sync(0xffffffffu, v, o);
        if (lane >= o) v += t;
    }
    int wtotal = __shfl_sync(0xffffffffu, v, 31);
    int base = 0;
    if (lane == 31) base = atomicAdd(&g_total, wtotal);
    base = __shfl_sync(0xffffffffu, base, 31);
    int off = base + v - cnt;                       // exclusive within warp
    g_off[i] = off;
    g_end[i] = off + cnt;
    g_cnt[i] = 0;
    float d = g_deg[i];
    g_dinv[i] = rsqrtf(fmaxf(d, 1e-30f));           // deg >= 1 (self-loop)
}

// place edges into destination buckets with final norm
__global__ void k_place() {
    int e = blockIdx.x * blockDim.x + threadIdx.x;
    if (e >= E_EDGES) return;
    int rc = g_rc[e];
    int r = rc >> 13, c = rc & (N_NODES - 1);
    float m = g_dinv[r] * g_ew[e] * g_dinv[c];
    int pos = g_off[c] + atomicAdd(&g_cnt[c], 1);
    g_rm[pos] = make_uint2((unsigned)r, __float_as_uint(m));
}

// warp per destination node: L2 gather of xw rows, one coalesced store
__global__ void __launch_bounds__(256) k_gather(const float* __restrict__ b,
                                                float* __restrict__ out) {
    int warp = (blockIdx.x * blockDim.x + threadIdx.x) >> 5;
    int lane = threadIdx.x & 31;
    if (warp >= N_NODES) return;
    int c = warp;
    const float4* xw4 = (const float4*)g_xw;
    int j = g_off[c], e = g_end[c];
    float4 acc = make_float4(0.f, 0.f, 0.f, 0.f);
    for (; j + 1 < e; j += 2) {
        uint2 p0 = g_rm[j];
        uint2 p1 = g_rm[j + 1];
        float4 v0 = xw4[(size_t)p0.x * 32 + lane];
        float4 v1 = xw4[(size_t)p1.x * 32 + lane];
        float m0 = __uint_as_float(p0.y);
        float m1 = __uint_as_float(p1.y);
        acc.x += m0 * v0.x + m1 * v1.x;
        acc.y += m0 * v0.y + m1 * v1.y;
        acc.z += m0 * v0.z + m1 * v1.z;
        acc.w += m0 * v0.w + m1 * v1.w;
    }
    if (j < e) {
        uint2 p0 = g_rm[j];
        float4 v0 = xw4[(size_t)p0.x * 32 + lane];
        float m0 = __uint_as_float(p0.y);
        acc.x += m0 * v0.x; acc.y += m0 * v0.y;
        acc.z += m0 * v0.z; acc.w += m0 * v0.w;
    }
    float di = g_dinv[c];
    float sl = di * di;                       // self-loop weight
    float4 vs = xw4[(size_t)c * 32 + lane];
    float4 bb = ((const float4*)b)[lane];
    acc.x += sl * vs.x + bb.x;
    acc.y += sl * vs.y + bb.y;
    acc.z += sl * vs.z + bb.z;
    acc.w += sl * vs.w + bb.w;
    ((float4*)out)[(size_t)c * 32 + lane] = acc;
}

extern "C" void kernel_launch(void* const* d_in, const int* in_sizes, int n_in,
                              void* d_out, int out_size) {
    const float* x  = (const float*)d_in[0];
    const float* A  = (const float*)d_in[1];
    const int*   ei = (const int*)  d_in[2];
    const float* wl = (const float*)d_in[3];
    const float* Wm = (const float*)d_in[4];
    const float* b  = (const float*)d_in[5];
    float* out = (float*)d_out;

    k_init   <<<1, 1>>>(wl);
    k_prep   <<<E_EDGES / 256, 256>>>(ei);
    k_fused  <<<GEMM_BLOCKS + EDGE_BLOCKS, 128>>>(x, Wm, A, ei);
    k_offsets<<<N_NODES / 256, 256>>>();
    k_place  <<<E_EDGES / 256, 256>>>();
    k_gather <<<N_NODES / 8, 256>>>(b, out);
}